// round 7
// baseline (speedup 1.0000x reference)
#include <cuda_runtime.h>
#include <math.h>

#define BB 256
#define TT 512
#define II 128
#define HH 256
#define H2 512
#define H3 768
#define SMS 148
#define GRID 444          // 3 CTAs per SM
#define NTHR 128
#define GSTRIDE (GRID * NTHR)

typedef unsigned long long ull;

#define SA_BUF (32 * 34)   // ull units: [32 k][32 row-pairs + 2 pad]
#define SW_BUF (32 * 18)   // ull units: [32 k][16 dup cols + 2 pad]

enum { EPI_RAW = 0, EPI_BIAS = 1, EPI_TANH = 2 };

// ---------------- persistent device scratch (no allocations) ----------------
__device__ float g_W1t[H2 * H2];     // transposed weights: Wt[k][n] = W[n][k]
__device__ float g_W2t[H2 * H2];
__device__ float g_W3t[H2 * H2];
__device__ float g_WihT[HH * H3];
__device__ float g_WhhT[HH * H3];
__device__ float g_WcinT[II * HH];

__device__ float g_com[BB][H2];      // [c | c_in_t]
__device__ float g_a1p[2][BB][H2];   // K-split partials
__device__ float g_a2p[2][BB][H2];
__device__ float g_a3p[2][BB][H2];
__device__ float g_gi[BB][H3];
__device__ float g_gh[BB][H3];
__device__ float g_c[BB][HH];
__device__ float g_h[BB][HH];
__device__ float g_n[BB];

__device__ unsigned g_bar_count;
__device__ volatile unsigned g_bar_gen;

__device__ __forceinline__ void grid_sync() {
    __syncthreads();
    if (threadIdx.x == 0) {
        unsigned gen = g_bar_gen;
        __threadfence();
        if (atomicAdd(&g_bar_count, 1u) == GRID - 1) {
            g_bar_count = 0;
            __threadfence();
            g_bar_gen = gen + 1;
        } else {
            while (g_bar_gen == gen) __nanosleep(32);
        }
        __threadfence();
    }
    __syncthreads();
}

__device__ __forceinline__ float sigf(float x) { return 1.f / (1.f + expf(-x)); }

__device__ __forceinline__ ull pack2(float x, float y) {
    ull r; asm("mov.b64 %0,{%1,%2};" : "=l"(r) : "f"(x), "f"(y)); return r;
}
__device__ __forceinline__ void unpack2(ull v, float& x, float& y) {
    asm("mov.b64 {%0,%1},%2;" : "=f"(x), "=f"(y) : "l"(v));
}
__device__ __forceinline__ void fma2(ull& d, ull a, ull b) {
    asm("fma.rn.f32x2 %0, %1, %2, %0;" : "+l"(d) : "l"(a), "l"(b));
}

// -------------------------------------------------------------------------
// One 64x16 output tile of C = epi(A @ Wt). 128 threads, per-thread 4x2.
// A rows staged as natural (row,row+1) packed pairs with XOR-swizzle;
// W cols staged duplicated. Inner loop: 2 LDS.128 + 4 FFMA2 per kk.
// -------------------------------------------------------------------------
template<int EPI, bool COMBINE>
__device__ __noinline__ void gemm64x16(
    const float* __restrict__ A0, const float* __restrict__ A1,
    const float* __restrict__ kb, int lda, int koff,
    const float* __restrict__ Wt, int ldw, int colBase,
    const float* __restrict__ bias,
    float* __restrict__ C, int ldc, int rowBase, int nkt,
    ull* __restrict__ sA, ull* __restrict__ sW)
{
    const int tid = threadIdx.x;
    const int tx  = tid & 7;       // col pair (2 cols)
    const int ty  = tid >> 3;      // 0..15 -> rows 4ty..4ty+3
    const int sp  = tid >> 2;      // stage: row pair 0..31 / W k-row 0..31
    const int skq = tid & 3;       // stage: k-octet / col quad

    ull c00 = 0, c01 = 0, c10 = 0, c11 = 0;
    float4 x0, x1, y0, y1, wv;

#define LOAD_T(kt)                                                               \
    {                                                                            \
        int kg = koff + (kt) * 32;                                               \
        const float* ap = A0 + (size_t)(rowBase + 2 * sp) * lda + kg + skq * 8;  \
        x0 = ((const float4*)ap)[0];                                             \
        x1 = ((const float4*)ap)[1];                                             \
        y0 = ((const float4*)(ap + lda))[0];                                     \
        y1 = ((const float4*)(ap + lda))[1];                                     \
        if (COMBINE) {                                                           \
            const float* bp = A1 + (size_t)(rowBase + 2 * sp) * lda + kg + skq * 8; \
            float4 u0 = ((const float4*)bp)[0];                                  \
            float4 u1 = ((const float4*)bp)[1];                                  \
            float4 v0 = ((const float4*)(bp + lda))[0];                          \
            float4 v1 = ((const float4*)(bp + lda))[1];                          \
            float4 k0 = ((const float4*)(kb + kg + skq * 8))[0];                 \
            float4 k1 = ((const float4*)(kb + kg + skq * 8))[1];                 \
            x0.x = fmaxf(x0.x + u0.x + k0.x, 0.f);                               \
            x0.y = fmaxf(x0.y + u0.y + k0.y, 0.f);                               \
            x0.z = fmaxf(x0.z + u0.z + k0.z, 0.f);                               \
            x0.w = fmaxf(x0.w + u0.w + k0.w, 0.f);                               \
            x1.x = fmaxf(x1.x + u1.x + k1.x, 0.f);                               \
            x1.y = fmaxf(x1.y + u1.y + k1.y, 0.f);                               \
            x1.z = fmaxf(x1.z + u1.z + k1.z, 0.f);                               \
            x1.w = fmaxf(x1.w + u1.w + k1.w, 0.f);                               \
            y0.x = fmaxf(y0.x + v0.x + k0.x, 0.f);                               \
            y0.y = fmaxf(y0.y + v0.y + k0.y, 0.f);                               \
            y0.z = fmaxf(y0.z + v0.z + k0.z, 0.f);                               \
            y0.w = fmaxf(y0.w + v0.w + k0.w, 0.f);                               \
            y1.x = fmaxf(y1.x + v1.x + k1.x, 0.f);                               \
            y1.y = fmaxf(y1.y + v1.y + k1.y, 0.f);                               \
            y1.z = fmaxf(y1.z + v1.z + k1.z, 0.f);                               \
            y1.w = fmaxf(y1.w + v1.w + k1.w, 0.f);                               \
        }                                                                        \
        wv = *(const float4*)(Wt + (size_t)(kg + sp) * ldw + colBase + skq * 4); \
    }

#define STORE_T(bi)                                                              \
    {                                                                            \
        ull* as = sA + (bi) * SA_BUF;                                            \
        ull* ws = sW + (bi) * SW_BUF;                                            \
        int pph = sp ^ (skq << 3);                                               \
        as[(skq * 8 + 0) * 34 + pph] = pack2(x0.x, y0.x);                        \
        as[(skq * 8 + 1) * 34 + pph] = pack2(x0.y, y0.y);                        \
        as[(skq * 8 + 2) * 34 + pph] = pack2(x0.z, y0.z);                        \
        as[(skq * 8 + 3) * 34 + pph] = pack2(x0.w, y0.w);                        \
        as[(skq * 8 + 4) * 34 + pph] = pack2(x1.x, y1.x);                        \
        as[(skq * 8 + 5) * 34 + pph] = pack2(x1.y, y1.y);                        \
        as[(skq * 8 + 6) * 34 + pph] = pack2(x1.z, y1.z);                        \
        as[(skq * 8 + 7) * 34 + pph] = pack2(x1.w, y1.w);                        \
        ws[sp * 18 + skq * 4 + 0] = pack2(wv.x, wv.x);                           \
        ws[sp * 18 + skq * 4 + 1] = pack2(wv.y, wv.y);                           \
        ws[sp * 18 + skq * 4 + 2] = pack2(wv.z, wv.z);                           \
        ws[sp * 18 + skq * 4 + 3] = pack2(wv.w, wv.w);                           \
    }

    LOAD_T(0);
    STORE_T(0);
    __syncthreads();

    for (int kt = 0; kt < nkt; kt++) {
        if (kt + 1 < nkt) LOAD_T(kt + 1);
        {
            const ull* as = sA + (kt & 1) * SA_BUF;
            const ull* ws = sW + (kt & 1) * SW_BUF;
#pragma unroll
            for (int kk = 0; kk < 32; kk++) {
                int g = kk >> 3;
                ulonglong2 a = *(const ulonglong2*)&as[kk * 34 + ((2 * ty) ^ (g << 3))];
                ulonglong2 w = *(const ulonglong2*)&ws[kk * 18 + 2 * tx];
                fma2(c00, a.x, w.x);
                fma2(c01, a.x, w.y);
                fma2(c10, a.y, w.x);
                fma2(c11, a.y, w.y);
            }
        }
        if (kt + 1 < nkt) STORE_T((kt + 1) & 1);
        __syncthreads();
    }
#undef LOAD_T
#undef STORE_T

    // epilogue: rows rowBase+4ty..+3, cols colBase+2tx, +1
    float r0c0, r1c0, r2c0, r3c0, r0c1, r1c1, r2c1, r3c1;
    unpack2(c00, r0c0, r1c0);
    unpack2(c10, r2c0, r3c0);
    unpack2(c01, r0c1, r1c1);
    unpack2(c11, r2c1, r3c1);
    int cc = colBase + 2 * tx;
    if (EPI != EPI_RAW) {
        float b0 = bias[cc], b1v = bias[cc + 1];
        r0c0 += b0; r1c0 += b0; r2c0 += b0; r3c0 += b0;
        r0c1 += b1v; r1c1 += b1v; r2c1 += b1v; r3c1 += b1v;
        if (EPI == EPI_TANH) {
            r0c0 = tanhf(r0c0); r1c0 = tanhf(r1c0); r2c0 = tanhf(r2c0); r3c0 = tanhf(r3c0);
            r0c1 = tanhf(r0c1); r1c1 = tanhf(r1c1); r2c1 = tanhf(r2c1); r3c1 = tanhf(r3c1);
        }
    }
    float* cp = C + (size_t)(rowBase + 4 * ty) * ldc + cc;
    *(float2*)cp                = make_float2(r0c0, r0c1);
    *(float2*)(cp + ldc)        = make_float2(r1c0, r1c1);
    *(float2*)(cp + 2 * ldc)    = make_float2(r2c0, r2c1);
    *(float2*)(cp + 3 * ldc)    = make_float2(r3c0, r3c1);
}

struct P {
    const float *b1, *b2, *b3, *bih, *bhh;
};

// g-jobs: 192 per matrix, gq -> rt (0..3) x ct (0..47)
__device__ __forceinline__ void do_g(int gq, bool is_gi, const P& p, ull* sA, ull* sW)
{
    int rt = gq / 48, ct = gq % 48;
    if (is_gi)
        gemm64x16<EPI_BIAS, false>(&g_c[0][0], 0, 0, HH, 0, g_WihT, H3, ct * 16,
                                   p.bih, &g_gi[0][0], H3, rt * 64, 8, sA, sW);
    else
        gemm64x16<EPI_BIAS, false>(&g_h[0][0], 0, 0, HH, 0, g_WhhT, H3, ct * 16,
                                   p.bhh, &g_gh[0][0], H3, rt * 64, 8, sA, sW);
}

// phases 0..2: 384 jobs (256 a-layer + 128 g); phase 3: 384 g jobs
__device__ void exec_job(int ph, int j, const P& p, ull* sA, ull* sW)
{
    if (ph < 3 && j < 256) {
        int grp = j >> 5;                  // (rt, kh) group: consecutive jobs share A rows
        int rt = grp >> 1, kh = grp & 1, ct = j & 31;
        int rb = rt * 64, cb = ct * 16, ko = kh * 256;
        if (ph == 0)
            gemm64x16<EPI_RAW, false>(&g_com[0][0], 0, 0, H2, ko, g_W1t, H2, cb,
                                      0, &g_a1p[kh][0][0], H2, rb, 8, sA, sW);
        else if (ph == 1)
            gemm64x16<EPI_RAW, true>(&g_a1p[0][0][0], &g_a1p[1][0][0], p.b1, H2, ko,
                                     g_W2t, H2, cb, 0, &g_a2p[kh][0][0], H2, rb, 8, sA, sW);
        else
            gemm64x16<EPI_RAW, true>(&g_a2p[0][0][0], &g_a2p[1][0][0], p.b2, H2, ko,
                                     g_W3t, H2, cb, 0, &g_a3p[kh][0][0], H2, rb, 8, sA, sW);
    } else if (ph == 3) {
        if (j < 192) do_g(j, true, p, sA, sW);
        else         do_g(j - 192, false, p, sA, sW);
    } else {
        int q = j - 256;                                   // 0..127
        if (ph == 0)      do_g(q, true, p, sA, sW);        // gi 0..127
        else if (ph == 1) { if (q < 64) do_g(128 + q, true, p, sA, sW);   // gi 128..191
                            else        do_g(q - 64, false, p, sA, sW); } // gh 0..63
        else              do_g(64 + q, false, p, sA, sW);  // gh 64..191
    }
}

// per-SM balanced slot mapping: SMs 0..87 -> 3 jobs, 88..147 -> 2 jobs
__device__ __forceinline__ int slot_job(int bid)
{
    int s = bid % SMS, slot = bid / SMS;
    if (s < 88) return 3 * s + slot;
    return (slot < 2) ? (264 + 2 * (s - 88) + slot) : -1;
}

// =========================== persistent megakernel ===========================
__global__ void __launch_bounds__(NTHR, 3)
rnn_persistent(const float* __restrict__ input, const float* __restrict__ noise,
               const float* __restrict__ Wcin, const float* __restrict__ bcin,
               const float* __restrict__ W1, const float* __restrict__ b1,
               const float* __restrict__ W2, const float* __restrict__ b2,
               const float* __restrict__ W3, const float* __restrict__ b3,
               const float* __restrict__ W4, const float* __restrict__ b4,
               const float* __restrict__ Wih, const float* __restrict__ Whh,
               const float* __restrict__ bih, const float* __restrict__ bhh,
               float* __restrict__ outC, float* __restrict__ outH,
               float* __restrict__ outF)
{
    __shared__ __align__(16) ull sA[2 * SA_BUF];
    __shared__ __align__(16) ull sW[2 * SW_BUF];
    __shared__ float su[8];

    const int bid = blockIdx.x;
    const int tid = threadIdx.x;
    const int gt  = bid * NTHR + tid;

    P p { b1, b2, b3, bih, bhh };

    // -------- weight transposes (once) --------
    for (int i = gt; i < H2 * H2; i += GSTRIDE) {
        int k = i / H2, n = i % H2;
        g_W1t[i] = W1[(size_t)n * H2 + k];
        g_W2t[i] = W2[(size_t)n * H2 + k];
        g_W3t[i] = W3[(size_t)n * H2 + k];
    }
    for (int i = gt; i < HH * H3; i += GSTRIDE) {
        int k = i / H3, n = i % H3;
        g_WihT[i] = Wih[(size_t)n * HH + k];
        g_WhhT[i] = Whh[(size_t)n * HH + k];
    }
    for (int i = gt; i < II * HH; i += GSTRIDE) {
        int k = i / HH, n = i % HH;
        g_WcinT[i] = Wcin[(size_t)n * II + k];
    }
    grid_sync();

    // -------- prologue: c_in = tanh(x @ Wcin^T) -> c_concat (row = b*T+t) --------
    for (int j = bid; j < 32768; j += GRID) {
        int rt = j >> 4, ct = j & 15;
        gemm64x16<EPI_TANH, false>(input, 0, 0, II, 0, g_WcinT, HH, ct * 16,
                                   bcin, outC, HH, rt * 64, 4, sA, sW);
    }
    grid_sync();

    // -------- init state --------
    if (bid < BB) {
        int b = bid;
        for (int j = tid; j < HH; j += NTHR) {
            g_c[b][j] = 0.f;
            g_h[b][j] = 0.f;
            g_com[b][j] = 0.f;
            g_com[b][HH + j] = outC[(size_t)b * TT * HH + j];
        }
        if (tid == 0) g_n[b] = 0.f;
    }
    grid_sync();

    const int myjob = slot_job(bid);

    // -------- recurrent loop --------
    for (int t = 0; t < TT; t++) {
        if (myjob >= 0) exec_job(0, myjob, p, sA, sW);
        grid_sync();
        if (myjob >= 0) exec_job(1, myjob, p, sA, sW);
        grid_sync();
        if (myjob >= 0) exec_job(2, myjob, p, sA, sW);
        grid_sync();

        // -------- phase U --------
        if (bid < BB) {
            int b = bid;
            float part = 0.f;
#pragma unroll
            for (int q = 0; q < 4; q++) {
                int k = tid + q * NTHR;
                float v = g_a3p[0][b][k] + g_a3p[1][b][k] + b3[k];
                part += fmaxf(v, 0.f) * W4[k];
            }
#pragma unroll
            for (int sh = 16; sh > 0; sh >>= 1)
                part += __shfl_down_sync(0xffffffffu, part, sh);
            if ((tid & 31) == 0) su[tid >> 5] = part;
            __syncthreads();
            if (tid == 0) {
                float logit = b4[0] + su[0] + su[1] + su[2] + su[3];
                float u = noise[(size_t)t * BB + b];
                float logistic = logf(u) - log1pf(-u);
                float a = sigf((logit + logistic) * 10.f);   // / TEMP
                float nold = g_n[b];
                su[4] = a;
                su[5] = nold;
                g_n[b] = nold * (1.f - a) + 1.f;
            }
            __syncthreads();
            float alpha = su[4], nold = su[5];
            float nnew = nold * (1.f - alpha) + 1.f;
#pragma unroll
            for (int u2 = 0; u2 < 2; u2++) {
                int jj = tid + u2 * NTHR;
                float c = g_c[b][jj], h = g_h[b][jj];
                float cin = outC[(size_t)b * TT * HH + (size_t)t * HH + jj];
                float r  = sigf(g_gi[b][jj] + g_gh[b][jj]);
                float z  = sigf(g_gi[b][HH + jj] + g_gh[b][HH + jj]);
                float ng = tanhf(g_gi[b][2 * HH + jj] + r * g_gh[b][2 * HH + jj]);
                float hcand = (1.f - z) * ng + z * h;
                float hnew = h * (1.f - alpha) + alpha * hcand;
                float cnew = (c * nold * (1.f - alpha) + cin) / nnew;
                g_c[b][jj] = cnew;
                g_h[b][jj] = hnew;
                outH[(size_t)b * TT * HH + (size_t)t * HH + jj] = hnew;
                g_com[b][jj] = cnew;
                if (t + 1 < TT)
                    g_com[b][HH + jj] = outC[(size_t)b * TT * HH + (size_t)(t + 1) * HH + jj];
            }
        }
        grid_sync();
    }

    // -------- epilogue: h_final = gru_cell(c_T, h_T) --------
    if (myjob >= 0) exec_job(3, myjob, p, sA, sW);
    grid_sync();
    if (bid < BB) {
        int b = bid;
#pragma unroll
        for (int u2 = 0; u2 < 2; u2++) {
            int jj = tid + u2 * NTHR;
            float h = g_h[b][jj];
            float r  = sigf(g_gi[b][jj] + g_gh[b][jj]);
            float z  = sigf(g_gi[b][HH + jj] + g_gh[b][HH + jj]);
            float ng = tanhf(g_gi[b][2 * HH + jj] + r * g_gh[b][2 * HH + jj]);
            outF[(size_t)b * HH + jj] = (1.f - z) * ng + z * h;
        }
    }
}

extern "C" void kernel_launch(void* const* d_in, const int* in_sizes, int n_in,
                              void* d_out, int out_size)
{
    const float* input = (const float*)d_in[0];
    const float* noise = (const float*)d_in[1];
    const float* Wcin  = (const float*)d_in[2];
    const float* bcin  = (const float*)d_in[3];
    const float* W1    = (const float*)d_in[4];
    const float* b1    = (const float*)d_in[5];
    const float* W2    = (const float*)d_in[6];
    const float* b2    = (const float*)d_in[7];
    const float* W3    = (const float*)d_in[8];
    const float* b3    = (const float*)d_in[9];
    const float* W4    = (const float*)d_in[10];
    const float* b4    = (const float*)d_in[11];
    const float* Wih   = (const float*)d_in[12];
    const float* Whh   = (const float*)d_in[13];
    const float* bih   = (const float*)d_in[14];
    const float* bhh   = (const float*)d_in[15];

    float* outC = (float*)d_out;                   // c_concat [B,T,H]
    float* outH = outC + (size_t)BB * TT * HH;     // h_concat [B,T,H]
    float* outF = outH + (size_t)BB * TT * HH;     // h_final  [B,H]

    rnn_persistent<<<GRID, NTHR>>>(input, noise, Wcin, bcin, W1, b1, W2, b2,
                                   W3, b3, W4, b4, Wih, Whh, bih, bhh,
                                   outC, outH, outF);
}